// round 1
// baseline (speedup 1.0000x reference)
#include <cuda_runtime.h>

#define B_ 8
#define L_ 1024
#define D_ 512
#define H_ 8
#define DK_ 64
#define M_ (B_*L_)

// Scratch (no allocations allowed)
__device__ float g_Q[B_*H_*L_*DK_];
__device__ float g_K[B_*H_*L_*DK_];
__device__ float g_V[B_*H_*L_*DK_];
__device__ float g_X[B_*L_*D_];

// ---------------------------------------------------------------------------
// C = A (M x 512) * W^T (512 x 512, W row-major N x K) + bias
// HEADS=1: write C in (B, H, L, DK) head-split layout; HEADS=0: row-major MxN.
// 64x64 block tile, 32 k-tile, 256 threads, 4x4 per thread.
// ---------------------------------------------------------------------------
template<int HEADS>
__global__ __launch_bounds__(256) void gemm_nt_kernel(
    const float* __restrict__ A, const float* __restrict__ W,
    const float* __restrict__ bias, float* __restrict__ C)
{
    __shared__ float As[32][68];
    __shared__ float Bs[32][68];
    const int tid = threadIdx.x;
    const int tx = tid & 15, ty = tid >> 4;
    const int m0 = blockIdx.y * 64, n0 = blockIdx.x * 64;

    float acc[4][4] = {};

#pragma unroll 1
    for (int kt = 0; kt < D_ / 32; ++kt) {
        __syncthreads();
#pragma unroll
        for (int p = 0; p < 2; ++p) {
            int e = (tid + p * 256) * 4;           // 0..2047
            int m = e >> 5, k = e & 31;
            float4 a4 = *(const float4*)&A[(size_t)(m0 + m) * D_ + kt * 32 + k];
            As[k + 0][m] = a4.x; As[k + 1][m] = a4.y;
            As[k + 2][m] = a4.z; As[k + 3][m] = a4.w;
            float4 b4 = *(const float4*)&W[(size_t)(n0 + m) * D_ + kt * 32 + k];
            Bs[k + 0][m] = b4.x; Bs[k + 1][m] = b4.y;
            Bs[k + 2][m] = b4.z; Bs[k + 3][m] = b4.w;
        }
        __syncthreads();
#pragma unroll
        for (int k = 0; k < 32; ++k) {
            float4 a = *(const float4*)&As[k][ty * 4];
            float4 b = *(const float4*)&Bs[k][tx * 4];
            acc[0][0] += a.x * b.x; acc[0][1] += a.x * b.y; acc[0][2] += a.x * b.z; acc[0][3] += a.x * b.w;
            acc[1][0] += a.y * b.x; acc[1][1] += a.y * b.y; acc[1][2] += a.y * b.z; acc[1][3] += a.y * b.w;
            acc[2][0] += a.z * b.x; acc[2][1] += a.z * b.y; acc[2][2] += a.z * b.z; acc[2][3] += a.z * b.w;
            acc[3][0] += a.w * b.x; acc[3][1] += a.w * b.y; acc[3][2] += a.w * b.z; acc[3][3] += a.w * b.w;
        }
    }

    const int nb = n0 + tx * 4;
    float4 bv = *(const float4*)&bias[nb];
#pragma unroll
    for (int ii = 0; ii < 4; ++ii) {
        int m = m0 + ty * 4 + ii;
        float4 r;
        r.x = acc[ii][0] + bv.x; r.y = acc[ii][1] + bv.y;
        r.z = acc[ii][2] + bv.z; r.w = acc[ii][3] + bv.w;
        if (HEADS) {
            int b = m >> 10, l = m & (L_ - 1);
            int h = nb >> 6, dk = nb & 63;
            *(float4*)&C[((size_t)(b * H_ + h) * L_ + l) * DK_ + dk] = r;
        } else {
            *(float4*)&C[(size_t)m * D_ + nb] = r;
        }
    }
}

// ---------------------------------------------------------------------------
// Flash-style attention with per-head distance bias.
// Block: one (b,h) x 64 query rows. TK=32 key tile, online softmax.
// ---------------------------------------------------------------------------
__global__ __launch_bounds__(256) void attn_kernel(
    const float* __restrict__ Q, const float* __restrict__ K,
    const float* __restrict__ V, const float* __restrict__ dist,
    const unsigned char* __restrict__ mask,
    const float* __restrict__ logwb, float* __restrict__ X)
{
    __shared__ float Qs[64][68];   // [d][i] transposed Q tile
    __shared__ float Ks[64][36];   // [d][j] transposed K tile
    __shared__ float Ss[32][68];   // [j][i] distance tile, then P tile
    __shared__ float Vs[32][68];   // [j][d] V tile
    __shared__ float red[16][64];  // reduction partials
    __shared__ float m_s[64], l_s[64], sc_s[64];

    const int tid = threadIdx.x;
    const int tx = tid & 15, ty = tid >> 4;
    const int bh = blockIdx.y;
    const int b = bh >> 3, h = bh & 7;
    const int q0 = blockIdx.x * 64;
    const float wb = __expf(logwb[h]);

    // Load Q tile transposed
    const float* Qb = Q + (size_t)(bh * L_ + q0) * DK_;
#pragma unroll
    for (int p = 0; p < 4; ++p) {
        int e = (tid + p * 256) * 4;   // 0..4095
        int i = e >> 6, d = e & 63;
        float4 v4 = *(const float4*)&Qb[i * DK_ + d];
        Qs[d + 0][i] = v4.x; Qs[d + 1][i] = v4.y;
        Qs[d + 2][i] = v4.z; Qs[d + 3][i] = v4.w;
    }
    if (tid < 64) { m_s[tid] = -1e30f; l_s[tid] = 0.f; }

    float o[4][4] = {};

    const float* Kb = K + (size_t)bh * L_ * DK_;
    const float* Vb = V + (size_t)bh * L_ * DK_;

    for (int k0 = 0; k0 < L_; k0 += 32) {
        __syncthreads();
        // Load K (transposed), V (natural)
#pragma unroll
        for (int p = 0; p < 2; ++p) {
            int e = (tid + p * 256) * 4;   // 0..2047
            int j = e >> 6, d = e & 63;
            float4 kv = *(const float4*)&Kb[(k0 + j) * DK_ + d];
            Ks[d + 0][j] = kv.x; Ks[d + 1][j] = kv.y;
            Ks[d + 2][j] = kv.z; Ks[d + 3][j] = kv.w;
            float4 vv = *(const float4*)&Vb[(k0 + j) * DK_ + d];
            *(float4*)&Vs[j][d] = vv;
        }
        // Distance/mask tile -> Ss[j][i] (coalesced along k)
#pragma unroll
        for (int p = 0; p < 2; ++p) {
            int e = (tid + p * 256) * 4;
            int i = e >> 5, j = e & 31;
            size_t base = (size_t)(b * L_ + q0 + i) * L_ + k0 + j;
            float4 dv = *(const float4*)&dist[base];
            uchar4 mv = *(const uchar4*)&mask[base];
            if (mv.x) dv.x = 1e30f;
            if (mv.y) dv.y = 1e30f;
            if (mv.z) dv.z = 1e30f;
            if (mv.w) dv.w = 1e30f;
            Ss[j + 0][i] = dv.x; Ss[j + 1][i] = dv.y;
            Ss[j + 2][i] = dv.z; Ss[j + 3][i] = dv.w;
        }
        __syncthreads();

        // S^T micro-tile: rows j = ty*2+{0,1}, cols i = tx*4+{0..3}
        const int j0 = ty * 2, i0 = tx * 4;
        float s0[4] = {}, s1[4] = {};
#pragma unroll
        for (int d = 0; d < 64; ++d) {
            float ka = Ks[d][j0], kb = Ks[d][j0 + 1];
            float4 q4 = *(const float4*)&Qs[d][i0];
            s0[0] += ka * q4.x; s0[1] += ka * q4.y; s0[2] += ka * q4.z; s0[3] += ka * q4.w;
            s1[0] += kb * q4.x; s1[1] += kb * q4.y; s1[2] += kb * q4.z; s1[3] += kb * q4.w;
        }
#pragma unroll
        for (int ii = 0; ii < 4; ++ii) {
            s0[ii] = s0[ii] * 0.125f - Ss[j0][i0 + ii] * wb;
            s1[ii] = s1[ii] * 0.125f - Ss[j0 + 1][i0 + ii] * wb;
        }
        __syncthreads();   // all dist reads done; red buffer free

        // Partial row max
#pragma unroll
        for (int ii = 0; ii < 4; ++ii)
            red[ty][i0 + ii] = fmaxf(s0[ii], s1[ii]);
        __syncthreads();
        if (tid < 64) {
            float mx = red[0][tid];
#pragma unroll
            for (int r = 1; r < 16; ++r) mx = fmaxf(mx, red[r][tid]);
            float mo = m_s[tid];
            float mn = fmaxf(mo, mx);
            sc_s[tid] = __expf(mo - mn);
            m_s[tid] = mn;
        }
        __syncthreads();

        // P = exp(S - m), write back to Ss, partial sums
#pragma unroll
        for (int ii = 0; ii < 4; ++ii) {
            float mm = m_s[i0 + ii];
            float p0 = __expf(s0[ii] - mm);
            float p1 = __expf(s1[ii] - mm);
            Ss[j0][i0 + ii] = p0;
            Ss[j0 + 1][i0 + ii] = p1;
            red[ty][i0 + ii] = p0 + p1;
        }
        __syncthreads();
        if (tid < 64) {
            float rs = 0.f;
#pragma unroll
            for (int r = 0; r < 16; ++r) rs += red[r][tid];
            l_s[tid] = l_s[tid] * sc_s[tid] + rs;
        }

        // O accumulate: rows i = ty*4+ii, cols d = tx*4+dd
        const int pi0 = ty * 4, pd0 = tx * 4;
#pragma unroll
        for (int ii = 0; ii < 4; ++ii) {
            float sc = sc_s[pi0 + ii];
            o[ii][0] *= sc; o[ii][1] *= sc; o[ii][2] *= sc; o[ii][3] *= sc;
        }
#pragma unroll
        for (int j = 0; j < 32; ++j) {
            float4 pp = *(const float4*)&Ss[j][pi0];
            float4 vv = *(const float4*)&Vs[j][pd0];
            o[0][0] += pp.x * vv.x; o[0][1] += pp.x * vv.y; o[0][2] += pp.x * vv.z; o[0][3] += pp.x * vv.w;
            o[1][0] += pp.y * vv.x; o[1][1] += pp.y * vv.y; o[1][2] += pp.y * vv.z; o[1][3] += pp.y * vv.w;
            o[2][0] += pp.z * vv.x; o[2][1] += pp.z * vv.y; o[2][2] += pp.z * vv.z; o[2][3] += pp.z * vv.w;
            o[3][0] += pp.w * vv.x; o[3][1] += pp.w * vv.y; o[3][2] += pp.w * vv.z; o[3][3] += pp.w * vv.w;
        }
    }
    __syncthreads();

    // Normalize and write X in (B, L, D) layout
#pragma unroll
    for (int ii = 0; ii < 4; ++ii) {
        int i = ty * 4 + ii;
        float inv = 1.f / l_s[i];
        float4 r;
        r.x = o[ii][0] * inv; r.y = o[ii][1] * inv;
        r.z = o[ii][2] * inv; r.w = o[ii][3] * inv;
        *(float4*)&X[(size_t)(b * L_ + q0 + i) * D_ + h * DK_ + tx * 4] = r;
    }
}

// ---------------------------------------------------------------------------
extern "C" void kernel_launch(void* const* d_in, const int* in_sizes, int n_in,
                              void* d_out, int out_size)
{
    const float* query = (const float*)d_in[0];
    const float* key_  = (const float*)d_in[1];
    const float* value = (const float*)d_in[2];
    const float* dist  = (const float*)d_in[3];
    const unsigned char* mask = (const unsigned char*)d_in[4];
    const float* Wq = (const float*)d_in[5];
    const float* bq = (const float*)d_in[6];
    const float* Wk = (const float*)d_in[7];
    const float* bk = (const float*)d_in[8];
    const float* Wv = (const float*)d_in[9];
    const float* bv = (const float*)d_in[10];
    const float* Wo = (const float*)d_in[11];
    const float* bo = (const float*)d_in[12];
    const float* logwb = (const float*)d_in[13];

    float *Qp, *Kp, *Vp, *Xp;
    cudaGetSymbolAddress((void**)&Qp, g_Q);
    cudaGetSymbolAddress((void**)&Kp, g_K);
    cudaGetSymbolAddress((void**)&Vp, g_V);
    cudaGetSymbolAddress((void**)&Xp, g_X);

    dim3 ggrid(D_ / 64, M_ / 64);   // (8, 128)
    gemm_nt_kernel<1><<<ggrid, 256>>>(query, Wq, bq, Qp);
    gemm_nt_kernel<1><<<ggrid, 256>>>(key_,  Wk, bk, Kp);
    gemm_nt_kernel<1><<<ggrid, 256>>>(value, Wv, bv, Vp);

    dim3 agrid(L_ / 64, B_ * H_);   // (16, 64)
    attn_kernel<<<agrid, 256>>>(Qp, Kp, Vp, dist, mask, logwb, Xp);

    gemm_nt_kernel<0><<<ggrid, 256>>>(Xp, Wo, bo, (float*)d_out);
}